// round 9
// baseline (speedup 1.0000x reference)
#include <cuda_runtime.h>

#define NB      64
#define NMEL    80
#define TFRAMES 1000
#define NDEC    1000
#define TENC    200
#define NSPK    100
#define NAUG    10

#define MEL_N    (NB * NMEL * TFRAMES)       // 5,120,000
#define MEL_N4   (MEL_N / 4)                 // 1,280,000
#define ALN_N    (NB * NDEC * TENC)          // 12,800,000
#define ALN_N4   (ALN_N / 4)                 // 3,200,000
#define GATE_N   (NB * TFRAMES)              // 64,000
#define GATE_N4  (GATE_N / 4)                // 16,000

#define THREADS     256
#define CTAS_PER_SM 8
// One exact wave at 8 blocks/SM: 148*8 = 1184
#define MEL_BLOCKS  640
#define ALN_BLOCKS  528
#define GATE_BLKS   14
#define GRID        (MEL_BLOCKS + ALN_BLOCKS + GATE_BLKS + 2)  // 1184

// accumulators: [0]=mel sumsq, [1]=gate sum, [2]=align sum,
//               [3]=speaker CE sum, [4]=augment CE sum
__device__ float        g_acc[5];
__device__ unsigned int g_done;

__device__ __forceinline__ float warpSum(float v) {
#pragma unroll
    for (int o = 16; o > 0; o >>= 1) v += __shfl_xor_sync(0xffffffffu, v, o);
    return v;
}

__device__ __forceinline__ float blockSum(float v) {
    __shared__ float s[32];
    int lane = threadIdx.x & 31, w = threadIdx.x >> 5;
    v = warpSum(v);
    if (lane == 0) s[w] = v;
    __syncthreads();
    int nw = blockDim.x >> 5;
    v = (threadIdx.x < nw) ? s[threadIdx.x] : 0.f;
    if (w == 0) v = warpSum(v);
    return v;
}

__device__ __forceinline__ float mel8(float4 av, float4 bv, float4 tv, float acc) {
    float d;
    d = av.x - tv.x; acc = fmaf(d, d, acc);
    d = bv.x - tv.x; acc = fmaf(d, d, acc);
    d = av.y - tv.y; acc = fmaf(d, d, acc);
    d = bv.y - tv.y; acc = fmaf(d, d, acc);
    d = av.z - tv.z; acc = fmaf(d, d, acc);
    d = bv.z - tv.z; acc = fmaf(d, d, acc);
    d = av.w - tv.w; acc = fmaf(d, d, acc);
    d = bv.w - tv.w; acc = fmaf(d, d, acc);
    return acc;
}

__device__ __forceinline__ float aln4(float4 v, int i, float acc) {
    const float invN = 1.f / NDEC;
    const float invT = 1.f / TENC;
    const float invK = 1.f / 0.4f;
    const int T4 = TENC / 4;  // 50
    int t4 = i % T4;
    int n  = (i / T4) % NDEC;
    float fn = n * invN;
    float ft = (t4 * 4) * invT;
    float d0 = fn - ft;
    float d1 = d0 - invT;
    float d2 = d1 - invT;
    float d3 = d2 - invT;
    acc += v.x * (1.f - __expf(-d0 * d0 * invK));
    acc += v.y * (1.f - __expf(-d1 * d1 * invK));
    acc += v.z * (1.f - __expf(-d2 * d2 * invK));
    acc += v.w * (1.f - __expf(-d3 * d3 * invK));
    return acc;
}

// cross-entropy: warp `w` handles rows w, w+8, ...; label = argmax(target row)
__device__ __forceinline__ void ce_warps(const float* __restrict__ logits,
                                         const float* __restrict__ tgt,
                                         int C, float* accp) {
    int lane = threadIdx.x & 31, w = threadIdx.x >> 5;
    int nwarps = blockDim.x >> 5;
    float acc = 0.f;
    for (int r = w; r < NB; r += nwarps) {
        const float* lg = logits + r * C;
        const float* tg = tgt + r * C;
        float bv = -1e30f; int bi = 0x7fffffff;
        for (int c = lane; c < C; c += 32) {
            float v = tg[c];
            if (v > bv) { bv = v; bi = c; }
        }
#pragma unroll
        for (int o = 16; o > 0; o >>= 1) {
            float ov = __shfl_xor_sync(0xffffffffu, bv, o);
            int   oi = __shfl_xor_sync(0xffffffffu, bi, o);
            if (ov > bv || (ov == bv && oi < bi)) { bv = ov; bi = oi; }
        }
        float m = -1e30f;
        for (int c = lane; c < C; c += 32) m = fmaxf(m, lg[c]);
#pragma unroll
        for (int o = 16; o > 0; o >>= 1) m = fmaxf(m, __shfl_xor_sync(0xffffffffu, m, o));
        float s = 0.f;
        for (int c = lane; c < C; c += 32) s += __expf(lg[c] - m);
        s = warpSum(s);
        if (lane == 0) acc += (m + logf(s)) - lg[bi];
    }
    if (lane == 0) {
        atomicAdd(accp, acc);
        __threadfence();
    }
}

__global__ void __launch_bounds__(THREADS, CTAS_PER_SM)
fused_loss_kernel(const float4* __restrict__ mel_a,
                  const float4* __restrict__ mel_b,
                  const float4* __restrict__ mel_t,
                  const float4* __restrict__ aln,
                  const float4* __restrict__ gate_o,
                  const float4* __restrict__ gate_t,
                  const float* __restrict__ spk_o,
                  const float* __restrict__ spk_t,
                  const float* __restrict__ aug_o,
                  const float* __restrict__ aug_t,
                  float* __restrict__ out) {
    const int bid = blockIdx.x;

    if (bid < MEL_BLOCKS) {
        // ---- mel MSE: sum (a-t)^2 + (b-t)^2, 2x unroll / dual acc ----
        float acc0 = 0.f, acc1 = 0.f;
        const int stride = MEL_BLOCKS * THREADS;
        int i = bid * THREADS + threadIdx.x;
        for (; i + stride < MEL_N4; i += 2 * stride) {
            int j = i + stride;
            float4 a0 = mel_a[i];
            float4 b0 = mel_b[i];
            float4 t0 = mel_t[i];
            float4 a1 = mel_a[j];
            float4 b1 = mel_b[j];
            float4 t1 = mel_t[j];
            acc0 = mel8(a0, b0, t0, acc0);
            acc1 = mel8(a1, b1, t1, acc1);
        }
        if (i < MEL_N4) {
            float4 a0 = mel_a[i];
            float4 b0 = mel_b[i];
            float4 t0 = mel_t[i];
            acc0 = mel8(a0, b0, t0, acc0);
        }
        float acc = blockSum(acc0 + acc1);
        if (threadIdx.x == 0) {
            atomicAdd(&g_acc[0], acc);
            __threadfence();
        }
    } else if (bid < MEL_BLOCKS + ALN_BLOCKS) {
        // ---- alignment: sum a[b,n,t] * (1 - exp(-((n/N - t/T)^2)/k)) ----
        float acc0 = 0.f, acc1 = 0.f;
        const int stride = ALN_BLOCKS * THREADS;
        int i = (bid - MEL_BLOCKS) * THREADS + threadIdx.x;
        for (; i + stride < ALN_N4; i += 2 * stride) {
            int j = i + stride;
            float4 v0 = aln[i];
            float4 v1 = aln[j];
            acc0 = aln4(v0, i, acc0);
            acc1 = aln4(v1, j, acc1);
        }
        if (i < ALN_N4) {
            float4 v0 = aln[i];
            acc0 = aln4(v0, i, acc0);
        }
        float acc = blockSum(acc0 + acc1);
        if (threadIdx.x == 0) {
            atomicAdd(&g_acc[2], acc);
            __threadfence();
        }
    } else if (bid < MEL_BLOCKS + ALN_BLOCKS + GATE_BLKS) {
        // ---- gate BCE: sum softplus(x) - x*y ----
        float acc = 0.f;
        const int stride = GATE_BLKS * THREADS;
        for (int i = (bid - MEL_BLOCKS - ALN_BLOCKS) * THREADS + threadIdx.x;
             i < GATE_N4; i += stride) {
            float4 x = gate_o[i], y = gate_t[i];
            acc += fmaxf(x.x, 0.f) + log1pf(__expf(-fabsf(x.x))) - x.x * y.x;
            acc += fmaxf(x.y, 0.f) + log1pf(__expf(-fabsf(x.y))) - x.y * y.y;
            acc += fmaxf(x.z, 0.f) + log1pf(__expf(-fabsf(x.z))) - x.z * y.z;
            acc += fmaxf(x.w, 0.f) + log1pf(__expf(-fabsf(x.w))) - x.w * y.w;
        }
        acc = blockSum(acc);
        if (threadIdx.x == 0) {
            atomicAdd(&g_acc[1], acc);
            __threadfence();
        }
    } else if (bid == GRID - 2) {
        ce_warps(spk_o, spk_t, NSPK, &g_acc[3]);
    } else {
        ce_warps(aug_o, aug_t, NAUG, &g_acc[4]);
    }

    // ---- completion count; last block finalizes and resets state ----
    __syncthreads();
    __shared__ bool isLast;
    if (threadIdx.x == 0) {
        unsigned prev = atomicAdd(&g_done, 1u);
        isLast = (prev == GRID - 1);
    }
    __syncthreads();
    if (isLast && threadIdx.x == 0) {
        float mel_loss   = __ldcg(&g_acc[0]) * (1.f / (float)MEL_N);
        float gate_loss  = __ldcg(&g_acc[1]) * (1.f / (float)GATE_N);
        float align_loss = fabsf(__ldcg(&g_acc[2])) * 0.0005f;
        float spk_loss   = __ldcg(&g_acc[3]) * (1.f / (float)NB);
        float aug_loss   = __ldcg(&g_acc[4]) * (1.f / (float)NB);
        float tmp   = mel_loss + gate_loss;
        float total = 10.f * tmp + 0.1f * (spk_loss + aug_loss) + align_loss;
        out[0] = total;
        out[1] = tmp;
        out[2] = spk_loss;
        out[3] = aug_loss;
        out[4] = align_loss;
#pragma unroll
        for (int i = 0; i < 5; i++) __stcg(&g_acc[i], 0.f);
        atomicExch(&g_done, 0u);
    }
}

extern "C" void kernel_launch(void* const* d_in, const int* in_sizes, int n_in,
                              void* d_out, int out_size) {
    const float* mel_out     = (const float*)d_in[0];
    const float* mel_post    = (const float*)d_in[1];
    const float* gate_out    = (const float*)d_in[2];
    const float* alignment   = (const float*)d_in[3];
    const float* speaker_out = (const float*)d_in[4];
    const float* augment_out = (const float*)d_in[5];
    const float* mel_tgt     = (const float*)d_in[6];
    const float* gate_tgt    = (const float*)d_in[7];
    const float* spk_tgt     = (const float*)d_in[8];
    const float* aug_tgt     = (const float*)d_in[9];

    fused_loss_kernel<<<GRID, THREADS>>>(
        (const float4*)mel_out, (const float4*)mel_post, (const float4*)mel_tgt,
        (const float4*)alignment,
        (const float4*)gate_out, (const float4*)gate_tgt,
        speaker_out, spk_tgt, augment_out, aug_tgt,
        (float*)d_out);
}

// round 10
// speedup vs baseline: 1.4370x; 1.4370x over previous
#include <cuda_runtime.h>

#define NB      64
#define NMEL    80
#define TFRAMES 1000
#define NDEC    1000
#define TENC    200
#define NSPK    100
#define NAUG    10

#define MEL_N    (NB * NMEL * TFRAMES)       // 5,120,000
#define MEL_N4   (MEL_N / 4)                 // 1,280,000
#define ALN_N    (NB * NDEC * TENC)          // 12,800,000
#define ALN_N4   (ALN_N / 4)                 // 3,200,000
#define GATE_N   (NB * TFRAMES)              // 64,000
#define GATE_N4  (GATE_N / 4)                // 16,000

#define THREADS     256
#define CTAS_PER_SM 7
#define GRID        (148 * CTAS_PER_SM)      // 1036, one exact wave

// ---- dynamic chunk space: tiny jobs first, then mel, then aln ----
#define CE_SPK_CHUNK  0
#define CE_AUG_CHUNK  1
#define GCHUNK        2048
#define GATE_CHUNKS   8                       // ceil(16000/2048)
#define GATE_BASE     2
#define MCHUNK        512
#define MEL_CHUNKS    (MEL_N4 / MCHUNK)       // 2500 exact
#define MEL_BASE      (GATE_BASE + GATE_CHUNKS)          // 10
#define ACHUNK        1536
#define ALN_CHUNKS    ((ALN_N4 + ACHUNK - 1) / ACHUNK)   // 2084
#define ALN_BASE      (MEL_BASE + MEL_CHUNKS)            // 2510
#define N_CHUNKS      (ALN_BASE + ALN_CHUNKS)            // 4594

// accumulators: [0]=mel sumsq, [1]=gate sum, [2]=align sum,
//               [3]=speaker CE sum, [4]=augment CE sum
__device__ float        g_acc[5];
__device__ unsigned int g_done;
__device__ unsigned int g_work;

__device__ __forceinline__ float warpSum(float v) {
#pragma unroll
    for (int o = 16; o > 0; o >>= 1) v += __shfl_xor_sync(0xffffffffu, v, o);
    return v;
}

// safe for repeated calls (sync protects shared reuse)
__device__ __forceinline__ float blockSum(float v) {
    __shared__ float s[8];
    int lane = threadIdx.x & 31, w = threadIdx.x >> 5;
    v = warpSum(v);
    __syncthreads();
    if (lane == 0) s[w] = v;
    __syncthreads();
    if (w == 0) {
        v = (lane < (THREADS >> 5)) ? s[lane] : 0.f;
        v = warpSum(v);
    }
    return v;
}

__device__ __forceinline__ float mel8(float4 av, float4 bv, float4 tv, float acc) {
    float d;
    d = av.x - tv.x; acc = fmaf(d, d, acc);
    d = bv.x - tv.x; acc = fmaf(d, d, acc);
    d = av.y - tv.y; acc = fmaf(d, d, acc);
    d = bv.y - tv.y; acc = fmaf(d, d, acc);
    d = av.z - tv.z; acc = fmaf(d, d, acc);
    d = bv.z - tv.z; acc = fmaf(d, d, acc);
    d = av.w - tv.w; acc = fmaf(d, d, acc);
    d = bv.w - tv.w; acc = fmaf(d, d, acc);
    return acc;
}

__device__ __forceinline__ float aln4(float4 v, int i, float acc) {
    const float invN = 1.f / NDEC;
    const float invT = 1.f / TENC;
    const float invK = 1.f / 0.4f;
    const int T4 = TENC / 4;  // 50
    int t4 = i % T4;
    int n  = (i / T4) % NDEC;
    float fn = n * invN;
    float ft = (t4 * 4) * invT;
    float d0 = fn - ft;
    float d1 = d0 - invT;
    float d2 = d1 - invT;
    float d3 = d2 - invT;
    acc += v.x * (1.f - __expf(-d0 * d0 * invK));
    acc += v.y * (1.f - __expf(-d1 * d1 * invK));
    acc += v.z * (1.f - __expf(-d2 * d2 * invK));
    acc += v.w * (1.f - __expf(-d3 * d3 * invK));
    return acc;
}

// cross-entropy: warp `w` handles rows w, w+8, ...; label = argmax(target row)
__device__ __forceinline__ void ce_warps(const float* __restrict__ logits,
                                         const float* __restrict__ tgt,
                                         int C, float* accp) {
    int lane = threadIdx.x & 31, w = threadIdx.x >> 5;
    int nwarps = THREADS >> 5;
    float acc = 0.f;
    for (int r = w; r < NB; r += nwarps) {
        const float* lg = logits + r * C;
        const float* tg = tgt + r * C;
        float bv = -1e30f; int bi = 0x7fffffff;
        for (int c = lane; c < C; c += 32) {
            float v = tg[c];
            if (v > bv) { bv = v; bi = c; }
        }
#pragma unroll
        for (int o = 16; o > 0; o >>= 1) {
            float ov = __shfl_xor_sync(0xffffffffu, bv, o);
            int   oi = __shfl_xor_sync(0xffffffffu, bi, o);
            if (ov > bv || (ov == bv && oi < bi)) { bv = ov; bi = oi; }
        }
        float m = -1e30f;
        for (int c = lane; c < C; c += 32) m = fmaxf(m, lg[c]);
#pragma unroll
        for (int o = 16; o > 0; o >>= 1) m = fmaxf(m, __shfl_xor_sync(0xffffffffu, m, o));
        float s = 0.f;
        for (int c = lane; c < C; c += 32) s += __expf(lg[c] - m);
        s = warpSum(s);
        if (lane == 0) acc += (m + logf(s)) - lg[bi];
    }
    if (lane == 0) atomicAdd(accp, acc);
}

__global__ void __launch_bounds__(THREADS, CTAS_PER_SM)
fused_loss_kernel(const float4* __restrict__ mel_a,
                  const float4* __restrict__ mel_b,
                  const float4* __restrict__ mel_t,
                  const float4* __restrict__ aln,
                  const float4* __restrict__ gate_o,
                  const float4* __restrict__ gate_t,
                  const float* __restrict__ spk_o,
                  const float* __restrict__ spk_t,
                  const float* __restrict__ aug_o,
                  const float* __restrict__ aug_t,
                  float* __restrict__ out) {
    __shared__ unsigned s_chunk;

    float accM0 = 0.f, accM1 = 0.f;   // mel
    float accA0 = 0.f, accA1 = 0.f;   // alignment
    float accG  = 0.f;                // gate

    for (;;) {
        if (threadIdx.x == 0) s_chunk = atomicAdd(&g_work, 1u);
        __syncthreads();
        const unsigned c = s_chunk;
        __syncthreads();   // allow s_chunk rewrite next iteration
        if (c >= N_CHUNKS) break;

        if (c >= ALN_BASE) {
            // ---- alignment chunk: 1536 float4 ----
            int base = (int)(c - ALN_BASE) * ACHUNK;
#pragma unroll
            for (int k = 0; k < ACHUNK; k += 2 * THREADS) {
                int i0 = base + k + threadIdx.x;
                int i1 = i0 + THREADS;
                if (i1 < ALN_N4) {
                    float4 v0 = __ldcs(&aln[i0]);
                    float4 v1 = __ldcs(&aln[i1]);
                    accA0 = aln4(v0, i0, accA0);
                    accA1 = aln4(v1, i1, accA1);
                } else if (i0 < ALN_N4) {
                    float4 v0 = __ldcs(&aln[i0]);
                    accA0 = aln4(v0, i0, accA0);
                }
            }
        } else if (c >= MEL_BASE) {
            // ---- mel chunk: 512 float4 (exact, no bounds checks) ----
            int i0 = (int)(c - MEL_BASE) * MCHUNK + threadIdx.x;
            int i1 = i0 + THREADS;
            float4 a0 = __ldcs(&mel_a[i0]);
            float4 b0 = __ldcs(&mel_b[i0]);
            float4 t0 = __ldcs(&mel_t[i0]);
            float4 a1 = __ldcs(&mel_a[i1]);
            float4 b1 = __ldcs(&mel_b[i1]);
            float4 t1 = __ldcs(&mel_t[i1]);
            accM0 = mel8(a0, b0, t0, accM0);
            accM1 = mel8(a1, b1, t1, accM1);
        } else if (c >= GATE_BASE) {
            // ---- gate BCE chunk: 2048 float4 ----
            int base = (int)(c - GATE_BASE) * GCHUNK;
#pragma unroll
            for (int k = 0; k < GCHUNK; k += THREADS) {
                int i = base + k + threadIdx.x;
                if (i < GATE_N4) {
                    float4 x = gate_o[i], y = gate_t[i];
                    accG += fmaxf(x.x, 0.f) + log1pf(__expf(-fabsf(x.x))) - x.x * y.x;
                    accG += fmaxf(x.y, 0.f) + log1pf(__expf(-fabsf(x.y))) - x.y * y.y;
                    accG += fmaxf(x.z, 0.f) + log1pf(__expf(-fabsf(x.z))) - x.z * y.z;
                    accG += fmaxf(x.w, 0.f) + log1pf(__expf(-fabsf(x.w))) - x.w * y.w;
                }
            }
        } else if (c == CE_SPK_CHUNK) {
            ce_warps(spk_o, spk_t, NSPK, &g_acc[3]);
        } else {
            ce_warps(aug_o, aug_t, NAUG, &g_acc[4]);
        }
    }

    // ---- fold local accumulators ----
    float m = blockSum(accM0 + accM1);
    float a = blockSum(accA0 + accA1);
    float g = blockSum(accG);
    if (threadIdx.x == 0) {
        if (m != 0.f) atomicAdd(&g_acc[0], m);
        if (a != 0.f) atomicAdd(&g_acc[2], a);
        if (g != 0.f) atomicAdd(&g_acc[1], g);
        __threadfence();
    }

    // ---- completion count; last block finalizes and resets state ----
    __syncthreads();
    __shared__ bool isLast;
    if (threadIdx.x == 0) {
        unsigned prev = atomicAdd(&g_done, 1u);
        isLast = (prev == GRID - 1);
    }
    __syncthreads();
    if (isLast && threadIdx.x == 0) {
        float mel_loss   = __ldcg(&g_acc[0]) * (1.f / (float)MEL_N);
        float gate_loss  = __ldcg(&g_acc[1]) * (1.f / (float)GATE_N);
        float align_loss = fabsf(__ldcg(&g_acc[2])) * 0.0005f;
        float spk_loss   = __ldcg(&g_acc[3]) * (1.f / (float)NB);
        float aug_loss   = __ldcg(&g_acc[4]) * (1.f / (float)NB);
        float tmp   = mel_loss + gate_loss;
        float total = 10.f * tmp + 0.1f * (spk_loss + aug_loss) + align_loss;
        out[0] = total;
        out[1] = tmp;
        out[2] = spk_loss;
        out[3] = aug_loss;
        out[4] = align_loss;
        // reset device state for next graph replay
#pragma unroll
        for (int i = 0; i < 5; i++) __stcg(&g_acc[i], 0.f);
        atomicExch(&g_work, 0u);
        atomicExch(&g_done, 0u);
    }
}

extern "C" void kernel_launch(void* const* d_in, const int* in_sizes, int n_in,
                              void* d_out, int out_size) {
    const float* mel_out     = (const float*)d_in[0];
    const float* mel_post    = (const float*)d_in[1];
    const float* gate_out    = (const float*)d_in[2];
    const float* alignment   = (const float*)d_in[3];
    const float* speaker_out = (const float*)d_in[4];
    const float* augment_out = (const float*)d_in[5];
    const float* mel_tgt     = (const float*)d_in[6];
    const float* gate_tgt    = (const float*)d_in[7];
    const float* spk_tgt     = (const float*)d_in[8];
    const float* aug_tgt     = (const float*)d_in[9];

    fused_loss_kernel<<<GRID, THREADS>>>(
        (const float4*)mel_out, (const float4*)mel_post, (const float4*)mel_tgt,
        (const float4*)alignment,
        (const float4*)gate_out, (const float4*)gate_tgt,
        speaker_out, spk_tgt, augment_out, aug_tgt,
        (float*)d_out);
}